// round 2
// baseline (speedup 1.0000x reference)
#include <cuda_runtime.h>
#include <cuda_bf16.h>
#include <stdint.h>

#define NB 512
#define NS 2048
#define NE 64
#define NP 32
#define NH 64
#define KD 96
#define TILE 128
#define NTILES 16
#define KPAD 104
#define NEG_F (-4294967296.0f)   /* fp32(-2^32+1) */

__device__ __forceinline__ float fast_tanh(float x) {
    float e = __expf(2.0f * x);
    return 1.0f - __fdividef(2.0f, e + 1.0f);
}

// Split fp32 pair into bf16-hi pair (bit truncation) + bf16-lo pair (RN of residual).
__device__ __forceinline__ void cvt_pair(float2 v, uint32_t &hi, uint32_t &lo) {
    uint32_t bx = __float_as_uint(v.x);
    uint32_t by = __float_as_uint(v.y);
    hi = __byte_perm(bx, by, 0x7632);   // packed {bf16(y.hi), bf16(x.hi)}
    float lx = v.x - __uint_as_float(bx & 0xffff0000u);
    float ly = v.y - __uint_as_float(by & 0xffff0000u);
    asm("cvt.rn.bf16x2.f32 %0, %1, %2;" : "=r"(lo) : "f"(ly), "f"(lx));
}

#define MMA_BF16(d, a, bb0, bb1)                                          \
    asm volatile(                                                          \
        "mma.sync.aligned.m16n8k16.row.col.f32.bf16.bf16.f32 "             \
        "{%0,%1,%2,%3},{%4,%5,%6,%7},{%8,%9},{%0,%1,%2,%3};"               \
        : "+f"((d)[0]), "+f"((d)[1]), "+f"((d)[2]), "+f"((d)[3])           \
        : "r"((a)[0]), "r"((a)[1]), "r"((a)[2]), "r"((a)[3]),              \
          "r"(bb0), "r"(bb1))

__global__ void __launch_bounds__(128, 3) i2i_kernel(
    const float* __restrict__ seq_items, const float* __restrict__ seq_pos,
    const float* __restrict__ target, const float* __restrict__ Wp,
    const float* __restrict__ We, const float* __restrict__ Wc,
    const float* __restrict__ bias, const float* __restrict__ zv,
    const int* __restrict__ seq_len, float* __restrict__ out)
{
    __shared__ __nv_bfloat16 wt_hi[NH * KPAD];
    __shared__ __nv_bfloat16 wt_lo[NH * KPAD];
    __shared__ float c_s[NH], z_s[NH];
    __shared__ float a_s[TILE], p_s[TILE];
    __shared__ float redA[4], redB[4];
    __shared__ float st[4];   // 0:m  1:l  2:r  3:scale
    __shared__ float u_s[TILE];

    const int b = blockIdx.x;
    const int tid = threadIdx.x;
    const int warp = tid >> 5, lane = tid & 31;
    const int g = lane >> 2, tig = lane & 3;

    // --- W = [We; Wp] -> bf16 hi/lo, transposed [n][k], padded stride ---
    for (int i = tid; i < KD * NH; i += 128) {
        int k = i >> 6, n = i & 63;
        float w = (k < NE) ? We[k * NH + n] : Wp[(k - NE) * NH + n];
        uint32_t bw = __float_as_uint(w);
        wt_hi[n * KPAD + k] = __ushort_as_bfloat16((unsigned short)(bw >> 16));
        wt_lo[n * KPAD + k] = __float2bfloat16(w - __uint_as_float(bw & 0xffff0000u));
    }
    // --- c[h] = target_b @ Wc + bias (fp32) ---
    if (tid < NH) {
        float a = bias[tid];
        const float* tg = target + b * 64;
        #pragma unroll 8
        for (int d = 0; d < 64; d++) a = fmaf(tg[d], Wc[d * NH + tid], a);
        c_s[tid] = a;
        z_s[tid] = zv[tid];
    }
    if (tid == 0) {
        st[0] = -__int_as_float(0x7f800000);  // m = -inf
        st[1] = 0.f; st[2] = 0.f; st[3] = 0.f;
    }
    __syncthreads();

    const int L = seq_len[b];
    const float* Xi = seq_items + (size_t)b * NS * NE;
    const float* Xp = seq_pos   + (size_t)b * NS * NP;
    float u_loc = 0.f;
    const int e_id = tid & 63, e_half = tid >> 6;

    for (int tile = 0; tile < NTILES; ++tile) {
        float acc[2][8][4];
        #pragma unroll
        for (int mi = 0; mi < 2; mi++)
            #pragma unroll
            for (int nt = 0; nt < 8; nt++)
                #pragma unroll
                for (int q = 0; q < 4; q++) acc[mi][nt][q] = 0.f;

        uint32_t Ah[2][2][4], Al[2][2][4];
        const int trow = tile * TILE + warp * 32;

        #define LOAD_A(KS, BUF)                                                  \
        {                                                                        \
            _Pragma("unroll")                                                    \
            for (int mi = 0; mi < 2; mi++) {                                     \
                int r0 = trow + mi * 16 + g;                                     \
                const float* bp = ((KS) < 4) ? Xi : Xp;                          \
                int ld = ((KS) < 4) ? NE : NP;                                   \
                int ci = ((KS) < 4) ? ((KS) * 16 + 2 * tig)                      \
                                    : (((KS) - 4) * 16 + 2 * tig);               \
                const float* p0 = bp + (size_t)r0 * ld + ci;                     \
                const float* p1 = bp + (size_t)(r0 + 8) * ld + ci;               \
                float2 v00 = *(const float2*)p0;                                 \
                float2 v10 = *(const float2*)p1;                                 \
                float2 v01 = *(const float2*)(p0 + 8);                           \
                float2 v11 = *(const float2*)(p1 + 8);                           \
                cvt_pair(v00, Ah[BUF][mi][0], Al[BUF][mi][0]);                   \
                cvt_pair(v10, Ah[BUF][mi][1], Al[BUF][mi][1]);                   \
                cvt_pair(v01, Ah[BUF][mi][2], Al[BUF][mi][2]);                   \
                cvt_pair(v11, Ah[BUF][mi][3], Al[BUF][mi][3]);                   \
            }                                                                    \
        }

        LOAD_A(0, 0);
        #pragma unroll
        for (int ks = 0; ks < 6; ks++) {
            const int cur = ks & 1;
            if (ks < 5) LOAD_A(ks + 1, cur ^ 1);
            #pragma unroll
            for (int nt = 0; nt < 8; nt++) {
                int widx = (nt * 8 + g) * KPAD + ks * 16 + 2 * tig;
                uint32_t bh0 = *(const uint32_t*)(wt_hi + widx);
                uint32_t bh1 = *(const uint32_t*)(wt_hi + widx + 8);
                uint32_t bl0 = *(const uint32_t*)(wt_lo + widx);
                uint32_t bl1 = *(const uint32_t*)(wt_lo + widx + 8);
                #pragma unroll
                for (int mi = 0; mi < 2; mi++) {
                    MMA_BF16(acc[mi][nt], Ah[cur][mi], bh0, bh1);   // hi*hi
                    MMA_BF16(acc[mi][nt], Al[cur][mi], bh0, bh1);   // lo*hi
                    MMA_BF16(acc[mi][nt], Ah[cur][mi], bl0, bl1);   // hi*lo
                }
            }
        }
        #undef LOAD_A

        // --- epilogue: a[t] = sum_h z_h * tanh(Y[t,h] + c_h) ---
        #pragma unroll
        for (int mi = 0; mi < 2; mi++) {
            float part0 = 0.f, part1 = 0.f;
            #pragma unroll
            for (int nt = 0; nt < 8; nt++) {
                int col = nt * 8 + 2 * tig;
                float c0 = c_s[col], c1 = c_s[col + 1];
                float z0 = z_s[col], z1 = z_s[col + 1];
                part0 += z0 * fast_tanh(acc[mi][nt][0] + c0) + z1 * fast_tanh(acc[mi][nt][1] + c1);
                part1 += z0 * fast_tanh(acc[mi][nt][2] + c0) + z1 * fast_tanh(acc[mi][nt][3] + c1);
            }
            part0 += __shfl_xor_sync(0xffffffffu, part0, 1);
            part0 += __shfl_xor_sync(0xffffffffu, part0, 2);
            part1 += __shfl_xor_sync(0xffffffffu, part1, 1);
            part1 += __shfl_xor_sync(0xffffffffu, part1, 2);
            if (tig == 0) {
                a_s[warp * 32 + mi * 16 + g]     = part0;
                a_s[warp * 32 + mi * 16 + 8 + g] = part1;
            }
        }
        __syncthreads();

        // --- online softmax bookkeeping ---
        int tglob = tile * TILE + tid;
        float araw = a_s[tid];
        bool inm = tglob < L;
        float am = inm ? araw : NEG_F;
        float rp = inm ? araw : 0.f;
        float mx = am, sm = rp;
        #pragma unroll
        for (int o = 16; o > 0; o >>= 1) {
            mx = fmaxf(mx, __shfl_xor_sync(0xffffffffu, mx, o));
            sm += __shfl_xor_sync(0xffffffffu, sm, o);
        }
        if (lane == 0) { redA[warp] = mx; redB[warp] = sm; }
        __syncthreads();
        if (tid == 0) {
            float tmax = fmaxf(fmaxf(redA[0], redA[1]), fmaxf(redA[2], redA[3]));
            st[2] += redB[0] + redB[1] + redB[2] + redB[3];
            float mo = st[0];
            float mn = fmaxf(mo, tmax);
            st[0] = mn;
            st[3] = __expf(mo - mn);
        }
        __syncthreads();
        float mn = st[0], sc = st[3];
        float p = __expf(am - mn);
        p_s[tid] = p;
        float sp = p;
        #pragma unroll
        for (int o = 16; o > 0; o >>= 1) sp += __shfl_xor_sync(0xffffffffu, sp, o);
        if (lane == 0) redB[warp] = sp;
        __syncthreads();
        if (tid == 0) st[1] = st[1] * sc + (redB[0] + redB[1] + redB[2] + redB[3]);

        // --- u accumulation: u[e] += p_t * items[t][e] (tile rows are L2-hot) ---
        u_loc *= sc;
        const float* xr = Xi + (size_t)(tile * TILE + e_half * 64) * NE + e_id;
        #pragma unroll 16
        for (int j = 0; j < 64; j++)
            u_loc = fmaf(p_s[e_half * 64 + j], xr[(size_t)j * NE], u_loc);
    }

    __syncthreads();
    u_s[tid] = u_loc;
    __syncthreads();
    if (tid < NH) {
        out[b * NH + tid] = (u_s[tid] + u_s[64 + tid]) / st[1];
    }
    if (tid == 64) out[NB * NH + b] = st[2];
}

extern "C" void kernel_launch(void* const* d_in, const int* in_sizes, int n_in,
                              void* d_out, int out_size) {
    const float* seq_items = (const float*)d_in[0];
    const float* seq_pos   = (const float*)d_in[1];
    const float* target    = (const float*)d_in[2];
    const float* Wp        = (const float*)d_in[3];
    const float* We        = (const float*)d_in[4];
    const float* Wc        = (const float*)d_in[5];
    const float* bias      = (const float*)d_in[6];
    const float* zv        = (const float*)d_in[7];
    const int*   seq_len   = (const int*)d_in[8];
    float* out = (float*)d_out;

    i2i_kernel<<<NB, 128>>>(seq_items, seq_pos, target, Wp, We, Wc,
                            bias, zv, seq_len, out);
}

// round 3
// speedup vs baseline: 1.1423x; 1.1423x over previous
#include <cuda_runtime.h>
#include <cuda_bf16.h>
#include <stdint.h>

#define NB 512
#define NS 2048
#define NE 64
#define NP 32
#define NH 64
#define TILE 128
#define NTILES 16
#define NEG_F (-4294967296.0f)   /* fp32(-2^32+1) */

__device__ __forceinline__ float fast_tanh(float x) {
    float e = __expf(2.0f * x);
    return 1.0f - __fdividef(2.0f, e + 1.0f);
}

// Split two fp32 into packed bf16-hi pair (truncation) + bf16-lo pair (residual, RN).
__device__ __forceinline__ void cvt_pair(float x, float y, uint32_t &hi, uint32_t &lo) {
    uint32_t bx = __float_as_uint(x), by = __float_as_uint(y);
    hi = __byte_perm(bx, by, 0x7632);          // {bf16(y), bf16(x)}, x in low half
    float lx = x - __uint_as_float(bx & 0xffff0000u);
    float ly = y - __uint_as_float(by & 0xffff0000u);
    asm("cvt.rn.bf16x2.f32 %0, %1, %2;" : "=r"(lo) : "f"(ly), "f"(lx));
}

#define MMA_BF16(d, a, bb0, bb1)                                          \
    asm volatile(                                                          \
        "mma.sync.aligned.m16n8k16.row.col.f32.bf16.bf16.f32 "             \
        "{%0,%1,%2,%3},{%4,%5,%6,%7},{%8,%9},{%0,%1,%2,%3};"               \
        : "+f"((d)[0]), "+f"((d)[1]), "+f"((d)[2]), "+f"((d)[3])           \
        : "r"((a)[0]), "r"((a)[1]), "r"((a)[2]), "r"((a)[3]),              \
          "r"(bb0), "r"(bb1))

__global__ void __launch_bounds__(256, 2) i2i_kernel(
    const float* __restrict__ seq_items, const float* __restrict__ seq_pos,
    const float* __restrict__ target, const float* __restrict__ Wp,
    const float* __restrict__ We, const float* __restrict__ Wc,
    const float* __restrict__ bias, const float* __restrict__ zv,
    const int* __restrict__ seq_len, float* __restrict__ out)
{
    // W fragments pre-swizzled into exact MMA B-fragment order:
    // wf[(ks*8 + nt)*32 + lane] = {bh0, bh1, bl0, bl1}
    __shared__ uint4  wf[6 * 8 * 32];          // 24 KB
    __shared__ float4 czcz[32];                // {c[2j],z[2j],c[2j+1],z[2j+1]}
    __shared__ float  a_s[2][TILE];            // double-buffered scores
    __shared__ float  p_sw[8][16];             // warp-private p slices
    __shared__ float  u_sm[8 * 64];            // u partials per warp
    __shared__ float  lr_s[2];                 // final l, r

    const int b = blockIdx.x;
    const int tid = threadIdx.x;
    const int warp = tid >> 5, lane = tid & 31;
    const int g = lane >> 2, tig = lane & 3;

    // ---- prologue: c[h] = target_b @ Wc + bias, interleaved with z ----
    if (tid < NH) {
        float a = bias[tid];
        const float* tg = target + b * 64;
        #pragma unroll 8
        for (int d = 0; d < 64; d++) a = fmaf(tg[d], Wc[d * NH + tid], a);
        float zval = zv[tid];
        ((float2*)czcz)[tid] = make_float2(a, zval);   // czcz[j] packs (c,z),(c,z)
    }
    // ---- prologue: build W fragments (hi/lo split, fragment-ordered) ----
    for (int i = tid; i < 6 * 8 * 32; i += 256) {
        int li = i & 31;
        int nt = (i >> 5) & 7;
        int ks = i >> 8;
        int gg = li >> 2, tt = li & 3;
        int n0 = nt * 8 + gg;
        int k0 = ks * 16 + 2 * tt;
        #define GETW(k) (((k) < NE) ? We[(k) * NH + n0] : Wp[((k) - NE) * NH + n0])
        float w00 = GETW(k0),     w01 = GETW(k0 + 1);
        float w10 = GETW(k0 + 8), w11 = GETW(k0 + 9);
        #undef GETW
        uint32_t bh0, bl0, bh1, bl1;
        cvt_pair(w00, w01, bh0, bl0);
        cvt_pair(w10, w11, bh1, bl1);
        wf[i] = make_uint4(bh0, bh1, bl0, bl1);
    }
    __syncthreads();

    const int L = seq_len[b];
    const float* Xi = seq_items + (size_t)b * NS * NE;
    const float* Xp = seq_pos   + (size_t)b * NS * NP;

    // per-warp replicated softmax state (uniform across lanes)
    float m = -__int_as_float(0x7f800000);   // -inf
    float l = 0.f, r = 0.f;
    float u0 = 0.f, u1 = 0.f;                // u[e=lane], u[e=lane+32]

    for (int tile = 0; tile < NTILES; ++tile) {
        const int par = tile & 1;
        float acc[8][4];
        #pragma unroll
        for (int nt = 0; nt < 8; nt++)
            #pragma unroll
            for (int q = 0; q < 4; q++) acc[nt][q] = 0.f;

        uint32_t Ah[2][4], Al[2][4];
        const int trow = tile * TILE + warp * 16;

        // A fragment load: rows trow+g, trow+g+8, cols from items (ks<4) or pos.
        #define LOAD_A(KS, BUF)                                                  \
        {                                                                        \
            int r0 = trow + g;                                                   \
            const float* bp = ((KS) < 4) ? Xi : Xp;                              \
            int ld = ((KS) < 4) ? NE : NP;                                       \
            int ci = ((KS) < 4) ? ((KS) * 16 + 2 * tig)                          \
                                : (((KS) - 4) * 16 + 2 * tig);                   \
            const float* p0 = bp + (size_t)r0 * ld + ci;                         \
            const float* p1 = bp + (size_t)(r0 + 8) * ld + ci;                   \
            float2 v00 = *(const float2*)p0;                                     \
            float2 v10 = *(const float2*)p1;                                     \
            float2 v01 = *(const float2*)(p0 + 8);                               \
            float2 v11 = *(const float2*)(p1 + 8);                               \
            cvt_pair(v00.x, v00.y, Ah[BUF][0], Al[BUF][0]);                      \
            cvt_pair(v10.x, v10.y, Ah[BUF][1], Al[BUF][1]);                      \
            cvt_pair(v01.x, v01.y, Ah[BUF][2], Al[BUF][2]);                      \
            cvt_pair(v11.x, v11.y, Ah[BUF][3], Al[BUF][3]);                      \
        }

        LOAD_A(0, 0);
        #pragma unroll
        for (int ks = 0; ks < 6; ks++) {
            const int cur = ks & 1;
            if (ks == 0) LOAD_A(1, 1);
            if (ks == 1) LOAD_A(2, 0);
            if (ks == 2) LOAD_A(3, 1);
            if (ks == 3) LOAD_A(4, 0);
            if (ks == 4) LOAD_A(5, 1);
            #pragma unroll
            for (int nt = 0; nt < 8; nt++) {
                uint4 f = wf[(ks * 8 + nt) * 32 + lane];
                MMA_BF16(acc[nt], Ah[cur], f.x, f.y);   // hi*hi
                MMA_BF16(acc[nt], Al[cur], f.x, f.y);   // lo*hi
                MMA_BF16(acc[nt], Ah[cur], f.z, f.w);   // hi*lo
            }
        }
        #undef LOAD_A

        // ---- epilogue: a[t] = sum_h z_h * tanh(Y[t,h] + c_h) ----
        float part0 = 0.f, part1 = 0.f;
        #pragma unroll
        for (int nt = 0; nt < 8; nt++) {
            float4 cz = czcz[nt * 4 + tig];
            part0 += cz.y * fast_tanh(acc[nt][0] + cz.x) + cz.w * fast_tanh(acc[nt][1] + cz.z);
            part1 += cz.y * fast_tanh(acc[nt][2] + cz.x) + cz.w * fast_tanh(acc[nt][3] + cz.z);
        }
        part0 += __shfl_xor_sync(0xffffffffu, part0, 1);
        part0 += __shfl_xor_sync(0xffffffffu, part0, 2);
        part1 += __shfl_xor_sync(0xffffffffu, part1, 1);
        part1 += __shfl_xor_sync(0xffffffffu, part1, 2);
        if (tig == 0) {
            a_s[par][warp * 16 + g]     = part0;
            a_s[par][warp * 16 + 8 + g] = part1;
        }
        __syncthreads();   // the ONE barrier per tile: a_s[par] ready

        // ---- per-warp redundant softmax reduction (register state) ----
        const int bt = tile * TILE;
        float a0 = a_s[par][lane];
        float a1 = a_s[par][lane + 32];
        float a2 = a_s[par][lane + 64];
        float a3 = a_s[par][lane + 96];
        float am0 = (bt + lane      < L) ? a0 : NEG_F;
        float am1 = (bt + lane + 32 < L) ? a1 : NEG_F;
        float am2 = (bt + lane + 64 < L) ? a2 : NEG_F;
        float am3 = (bt + lane + 96 < L) ? a3 : NEG_F;
        float raw = ((bt + lane      < L) ? a0 : 0.f) + ((bt + lane + 32 < L) ? a1 : 0.f)
                  + ((bt + lane + 64 < L) ? a2 : 0.f) + ((bt + lane + 96 < L) ? a3 : 0.f);
        float mx = fmaxf(fmaxf(am0, am1), fmaxf(am2, am3));
        #pragma unroll
        for (int o = 16; o > 0; o >>= 1) {
            mx  = fmaxf(mx, __shfl_xor_sync(0xffffffffu, mx, o));
            raw += __shfl_xor_sync(0xffffffffu, raw, o);
        }
        r += raw;
        float m_new = fmaxf(m, mx);
        float sc = __expf(m - m_new);
        float sp = __expf(am0 - m_new) + __expf(am1 - m_new)
                 + __expf(am2 - m_new) + __expf(am3 - m_new);
        #pragma unroll
        for (int o = 16; o > 0; o >>= 1) sp += __shfl_xor_sync(0xffffffffu, sp, o);
        l = l * sc + sp;
        m = m_new;

        // ---- own-row p (produced & consumed by this warp; no block sync) ----
        if (lane < 16) {
            int tok = bt + warp * 16 + lane;
            float av = a_s[par][warp * 16 + lane];
            float amv = (tok < L) ? av : NEG_F;
            p_sw[warp][lane] = __expf(amv - m_new);
        }
        __syncwarp();

        // ---- u accumulation over this warp's 16 rows (L1-hot) ----
        u0 *= sc; u1 *= sc;
        const float* xr = Xi + (size_t)(bt + warp * 16) * NE;
        #pragma unroll
        for (int j = 0; j < 16; j++) {
            float pf = p_sw[warp][j];
            u0 = fmaf(pf, xr[j * NE + lane], u0);
            u1 = fmaf(pf, xr[j * NE + lane + 32], u1);
        }
    }

    // ---- final reduction across warps ----
    u_sm[warp * 64 + lane]      = u0;
    u_sm[warp * 64 + lane + 32] = u1;
    if (tid == 0) { lr_s[0] = l; lr_s[1] = r; }
    __syncthreads();
    if (tid < NH) {
        float s = 0.f;
        #pragma unroll
        for (int w = 0; w < 8; w++) s += u_sm[w * 64 + tid];
        out[b * NH + tid] = s / lr_s[0];
    }
    if (tid == 64) out[NB * NH + b] = lr_s[1];
}

extern "C" void kernel_launch(void* const* d_in, const int* in_sizes, int n_in,
                              void* d_out, int out_size) {
    const float* seq_items = (const float*)d_in[0];
    const float* seq_pos   = (const float*)d_in[1];
    const float* target    = (const float*)d_in[2];
    const float* Wp        = (const float*)d_in[3];
    const float* We        = (const float*)d_in[4];
    const float* Wc        = (const float*)d_in[5];
    const float* bias      = (const float*)d_in[6];
    const float* zv        = (const float*)d_in[7];
    const int*   seq_len   = (const int*)d_in[8];
    float* out = (float*)d_out;

    i2i_kernel<<<NB, 256>>>(seq_items, seq_pos, target, Wp, We, Wc,
                            bias, zv, seq_len, out);
}

// round 5
// speedup vs baseline: 1.2427x; 1.0880x over previous
#include <cuda_runtime.h>
#include <cuda_bf16.h>
#include <stdint.h>

#define NB 512
#define NS 2048
#define NE 64
#define NP 32
#define NH 64
#define TILE 256
#define NTILES 8
#define NEG_F (-4294967296.0f)   /* fp32(-2^32+1) */

__device__ __forceinline__ float fast_tanh(float x) {
    float e = __expf(2.0f * x);
    return 1.0f - __fdividef(2.0f, e + 1.0f);
}

// Split two fp32 into packed bf16-hi pair (truncation) + bf16-lo pair (residual, RN).
__device__ __forceinline__ void cvt_pair(float x, float y, uint32_t &hi, uint32_t &lo) {
    uint32_t bx = __float_as_uint(x), by = __float_as_uint(y);
    hi = __byte_perm(bx, by, 0x7632);          // {bf16(y), bf16(x)}, x in low half
    float lx = x - __uint_as_float(bx & 0xffff0000u);
    float ly = y - __uint_as_float(by & 0xffff0000u);
    asm("cvt.rn.bf16x2.f32 %0, %1, %2;" : "=r"(lo) : "f"(ly), "f"(lx));
}

#define MMA_BF16(d, a, bb0, bb1)                                          \
    asm volatile(                                                          \
        "mma.sync.aligned.m16n8k16.row.col.f32.bf16.bf16.f32 "             \
        "{%0,%1,%2,%3},{%4,%5,%6,%7},{%8,%9},{%0,%1,%2,%3};"               \
        : "+f"((d)[0]), "+f"((d)[1]), "+f"((d)[2]), "+f"((d)[3])           \
        : "r"((a)[0]), "r"((a)[1]), "r"((a)[2]), "r"((a)[3]),              \
          "r"(bb0), "r"(bb1))

__global__ void __launch_bounds__(256, 2) i2i_kernel(
    const float* __restrict__ seq_items, const float* __restrict__ seq_pos,
    const float* __restrict__ target, const float* __restrict__ Wp,
    const float* __restrict__ We, const float* __restrict__ Wc,
    const float* __restrict__ bias, const float* __restrict__ zv,
    const int* __restrict__ seq_len, float* __restrict__ out)
{
    // W fragments in exact MMA B-fragment order: wf[(ks*8+nt)*32+lane] = {bh0,bh1,bl0,bl1}
    __shared__ uint4  wf[6 * 8 * 32];          // 24 KB
    __shared__ float4 czcz[32];                // {c[2j],z[2j],c[2j+1],z[2j+1]}
    __shared__ float  a_s[2][TILE];            // double-buffered scores
    __shared__ float  u_sm[8 * 64];            // u partials per warp

    const int b = blockIdx.x;
    const int tid = threadIdx.x;
    const int warp = tid >> 5, lane = tid & 31;
    const int g = lane >> 2, tig = lane & 3;

    // ---- prologue: c[h] = target_b @ Wc + bias ----
    if (tid < NH) {
        float a = bias[tid];
        const float* tg = target + b * 64;
        #pragma unroll 8
        for (int d = 0; d < 64; d++) a = fmaf(tg[d], Wc[d * NH + tid], a);
        ((float2*)czcz)[tid] = make_float2(a, zv[tid]);
    }
    // ---- prologue: W fragments (hi/lo split, fragment-ordered) ----
    for (int i = tid; i < 6 * 8 * 32; i += 256) {
        int li = i & 31;
        int nt = (i >> 5) & 7;
        int ks = i >> 8;
        int gg = li >> 2, tt = li & 3;
        int n0 = nt * 8 + gg;
        int k0 = ks * 16 + 2 * tt;
        #define GETW(k) (((k) < NE) ? We[(k) * NH + n0] : Wp[((k) - NE) * NH + n0])
        float w00 = GETW(k0),     w01 = GETW(k0 + 1);
        float w10 = GETW(k0 + 8), w11 = GETW(k0 + 9);
        #undef GETW
        uint32_t bh0, bl0, bh1, bl1;
        cvt_pair(w00, w01, bh0, bl0);
        cvt_pair(w10, w11, bh1, bl1);
        wf[i] = make_uint4(bh0, bh1, bl0, bl1);
    }
    __syncthreads();

    const int L = seq_len[b];
    const float* Xi = seq_items + (size_t)b * NS * NE;
    const float* Xp = seq_pos   + (size_t)b * NS * NP;

    float m = -__int_as_float(0x7f800000);   // -inf (warp-uniform, replicated)
    float l = 0.f, r = 0.f;
    float u0 = 0.f, u1 = 0.f;                // u[2*lane], u[2*lane+1]

    for (int tile = 0; tile < NTILES; ++tile) {
        const int par = tile & 1;
        float acc[2][8][4];
        #pragma unroll
        for (int mi = 0; mi < 2; mi++)
            #pragma unroll
            for (int nt = 0; nt < 8; nt++)
                #pragma unroll
                for (int q = 0; q < 4; q++) acc[mi][nt][q] = 0.f;

        const int trow = tile * TILE + warp * 32;   // this warp's 32 rows

        #pragma unroll
        for (int ks = 0; ks < 6; ks++) {
            // ---- A fragments for both M-blocks at this k-chunk ----
            uint32_t Ah[2][4], Al[2][4];
            const float* bp = (ks < 4) ? Xi : Xp;
            const int ld = (ks < 4) ? NE : NP;
            const int ci = ((ks < 4) ? ks * 16 : (ks - 4) * 16) + 2 * tig;
            #pragma unroll
            for (int mi = 0; mi < 2; mi++) {
                const float* p0 = bp + (size_t)(trow + mi * 16 + g) * ld + ci;
                const float* p1 = p0 + (size_t)8 * ld;
                float2 v00 = *(const float2*)p0;
                float2 v10 = *(const float2*)p1;
                float2 v01 = *(const float2*)(p0 + 8);
                float2 v11 = *(const float2*)(p1 + 8);
                cvt_pair(v00.x, v00.y, Ah[mi][0], Al[mi][0]);
                cvt_pair(v10.x, v10.y, Ah[mi][1], Al[mi][1]);
                cvt_pair(v01.x, v01.y, Ah[mi][2], Al[mi][2]);
                cvt_pair(v11.x, v11.y, Ah[mi][3], Al[mi][3]);
            }
            // ---- one B-fragment load feeds 6 MMAs ----
            #pragma unroll
            for (int nt = 0; nt < 8; nt++) {
                uint4 f = wf[(ks * 8 + nt) * 32 + lane];
                #pragma unroll
                for (int mi = 0; mi < 2; mi++) {
                    MMA_BF16(acc[mi][nt], Ah[mi], f.x, f.y);   // hi*hi
                    MMA_BF16(acc[mi][nt], Al[mi], f.x, f.y);   // lo*hi
                    MMA_BF16(acc[mi][nt], Ah[mi], f.z, f.w);   // hi*lo
                }
            }
        }

        // ---- epilogue: a[t] = sum_h z_h * tanh(Y[t,h] + c_h) ----
        #pragma unroll
        for (int mi = 0; mi < 2; mi++) {
            float part0 = 0.f, part1 = 0.f;
            #pragma unroll
            for (int nt = 0; nt < 8; nt++) {
                float4 cz = czcz[nt * 4 + tig];
                part0 += cz.y * fast_tanh(acc[mi][nt][0] + cz.x) + cz.w * fast_tanh(acc[mi][nt][1] + cz.z);
                part1 += cz.y * fast_tanh(acc[mi][nt][2] + cz.x) + cz.w * fast_tanh(acc[mi][nt][3] + cz.z);
            }
            part0 += __shfl_xor_sync(0xffffffffu, part0, 1);
            part0 += __shfl_xor_sync(0xffffffffu, part0, 2);
            part1 += __shfl_xor_sync(0xffffffffu, part1, 1);
            part1 += __shfl_xor_sync(0xffffffffu, part1, 2);
            if (tig == 0) {
                a_s[par][warp * 32 + mi * 16 + g]     = part0;
                a_s[par][warp * 32 + mi * 16 + 8 + g] = part1;
            }
        }
        __syncthreads();   // the one barrier per tile

        // ---- per-warp redundant softmax reduction (register state) ----
        const int bt = tile * TILE;
        float am[8], raw = 0.f, mx = NEG_F;
        #pragma unroll
        for (int j = 0; j < 8; j++) {
            float av = a_s[par][j * 32 + lane];
            bool inm = (bt + j * 32 + lane) < L;
            am[j] = inm ? av : NEG_F;
            raw += inm ? av : 0.f;
            mx = fmaxf(mx, am[j]);
        }
        #pragma unroll
        for (int o = 16; o > 0; o >>= 1) {
            mx  = fmaxf(mx, __shfl_xor_sync(0xffffffffu, mx, o));
            raw += __shfl_xor_sync(0xffffffffu, raw, o);
        }
        r += raw;
        float m_new = fmaxf(m, mx);
        float sc = __expf(m - m_new);
        float sp = 0.f;
        #pragma unroll
        for (int j = 0; j < 8; j++) sp += __expf(am[j] - m_new);
        #pragma unroll
        for (int o = 16; o > 0; o >>= 1) sp += __shfl_xor_sync(0xffffffffu, sp, o);
        l = l * sc + sp;
        m = m_new;

        // ---- own-row p in register, broadcast by shuffle ----
        {
            float av = a_s[par][warp * 32 + lane];
            float p_own = __expf((((bt + warp * 32 + lane) < L) ? av : NEG_F) - m_new);

            // ---- u accumulation over this warp's 32 rows (L1/L2-hot) ----
            u0 *= sc; u1 *= sc;
            const float* xr = Xi + (size_t)(bt + warp * 32) * NE + 2 * lane;
            #pragma unroll
            for (int j = 0; j < 32; j++) {
                float pf = __shfl_sync(0xffffffffu, p_own, j);
                float2 v = *(const float2*)(xr + (size_t)j * NE);
                u0 = fmaf(pf, v.x, u0);
                u1 = fmaf(pf, v.y, u1);
            }
        }
    }

    // ---- final reduction across warps ----
    u_sm[warp * 64 + 2 * lane]     = u0;
    u_sm[warp * 64 + 2 * lane + 1] = u1;
    __syncthreads();
    if (tid < NH) {
        float s = 0.f;
        #pragma unroll
        for (int w = 0; w < 8; w++) s += u_sm[w * 64 + tid];
        out[b * NH + tid] = s / l;     // l is identical across warps
    }
    if (tid == 64) out[NB * NH + b] = r;
}

extern "C" void kernel_launch(void* const* d_in, const int* in_sizes, int n_in,
                              void* d_out, int out_size) {
    const float* seq_items = (const float*)d_in[0];
    const float* seq_pos   = (const float*)d_in[1];
    const float* target    = (const float*)d_in[2];
    const float* Wp        = (const float*)d_in[3];
    const float* We        = (const float*)d_in[4];
    const float* Wc        = (const float*)d_in[5];
    const float* bias      = (const float*)d_in[6];
    const float* zv        = (const float*)d_in[7];
    const int*   seq_len   = (const int*)d_in[8];
    float* out = (float*)d_out;

    i2i_kernel<<<NB, 256>>>(seq_items, seq_pos, target, Wp, We, Wc,
                            bias, zv, seq_len, out);
}